// round 5
// baseline (speedup 1.0000x reference)
#include <cuda_runtime.h>
#include <cstdint>

#define BATCH 32
#define CH    64
#define OCH   64
#define HW    128
#define NPIX  16384
#define CONDN 16
#define KK    9

// ---------------- scratch (device globals; no allocation allowed) -------------
__device__ float g_S[BATCH * CH * KK];        // strided sums  [b][c][i*3+j]
__device__ float g_dw[BATCH * CH * KK];       // depthwise weights
__device__ float g_pw[BATCH * CH * OCH];      // pointwise, stored [b][c][o]
__device__ float g_db[BATCH * OCH];           // dynamic bias
__device__ float g_part[BATCH * OCH * 2];     // per-(b,o) partial sum / sumsq
__device__ float g_scale[OCH];
__device__ float g_shift[OCH];

// =============================================================================
// K1: strided partial sums S[b,c,i,j] = sum_{p,q=0..62} x[b,c,2p+i,2q+j]
// (conv3x3 stride2 VALID followed by global mean, with the mean commuted
//  through the conv sum)
// =============================================================================
__global__ void k_ssum(const float* __restrict__ x) {
    int bc = blockIdx.x;                       // b*64 + c
    const float* xp = x + (size_t)bc * NPIX;
    int tid = threadIdx.x;                     // 256
    int s = tid & 127;                         // fixed column per thread
    int rbase = tid >> 7;                      // 0 or 1 -> fixed row parity

    float a[9];
#pragma unroll
    for (int m = 0; m < 9; m++) a[m] = 0.f;

    bool se = (s & 1) == 0;
    bool j0 = se && (s <= 124);
    bool j1 = (!se) && (s <= 125);
    bool j2 = se && (s >= 2);

    for (int k = 0; k < 64; k++) {
        int r = rbase + 2 * k;
        float v = xp[r * HW + s];
        bool re = (r & 1) == 0;
        bool i0 = re && (r <= 124);
        bool i1 = (!re) && (r <= 125);
        bool i2 = re && (r >= 2);
        if (i0) { if (j0) a[0] += v; if (j1) a[1] += v; if (j2) a[2] += v; }
        if (i1) { if (j0) a[3] += v; if (j1) a[4] += v; if (j2) a[5] += v; }
        if (i2) { if (j0) a[6] += v; if (j1) a[7] += v; if (j2) a[8] += v; }
    }

#pragma unroll
    for (int m = 0; m < 9; m++)
#pragma unroll
        for (int off = 16; off > 0; off >>= 1)
            a[m] += __shfl_xor_sync(0xffffffffu, a[m], off);

    __shared__ float red[8][9];
    int lane = tid & 31, w = tid >> 5;
    if (lane == 0) {
#pragma unroll
        for (int m = 0; m < 9; m++) red[w][m] = a[m];
    }
    __syncthreads();
    if (tid < 9) {
        float t = 0.f;
#pragma unroll
        for (int w2 = 0; w2 < 8; w2++) t += red[w2][tid];
        g_S[bc * 9 + tid] = t;
    }
}

// =============================================================================
// K2: conditioning network + dynamic weight generators (one block per sample)
// =============================================================================
__global__ void k_cond(const float* __restrict__ cg_w1, const float* __restrict__ cg_b1,
                       const float* __restrict__ cg_w2, const float* __restrict__ cg_b2,
                       const float* __restrict__ wg_w,  const float* __restrict__ wg_b,
                       const float* __restrict__ pg_w,  const float* __restrict__ pg_b,
                       const float* __restrict__ bg_w,  const float* __restrict__ bg_b) {
    int b = blockIdx.x;
    int tid = threadIdx.x;   // 128
    __shared__ float Ssh[CH * KK];      // 576
    __shared__ float c1[CONDN];
    __shared__ float c2[CONDN];

    for (int i = tid; i < CH * KK; i += 128) Ssh[i] = g_S[b * (CH * KK) + i];
    __syncthreads();

    if (tid < CONDN) {
        // cond1[o] = relu( mean(conv) + b1 ) = relu( (w1 . S)/3969 + b1 )
        float m = 0.f;
        const float* w = cg_w1 + tid * (CH * KK);
        for (int i = 0; i < CH * KK; i++) m += w[i] * Ssh[i];
        m = m * (1.0f / 3969.0f) + cg_b1[tid];
        c1[tid] = fmaxf(m, 0.f);
    }
    __syncthreads();
    if (tid < CONDN) {
        float m = cg_b2[tid];
#pragma unroll
        for (int k = 0; k < CONDN; k++) m += cg_w2[tid * CONDN + k] * c1[k];
        c2[tid] = fmaxf(m, 0.f);
    }
    __syncthreads();

    // depthwise weights: 576 outputs
    for (int n = tid; n < CH * KK; n += 128) {
        float m = wg_b[n];
        const float* w = wg_w + n * CONDN;
#pragma unroll
        for (int k = 0; k < CONDN; k++) m += w[k] * c2[k];
        g_dw[b * (CH * KK) + n] = fmaxf(m, 0.f);
    }
    // pointwise weights: 4096 outputs, stored transposed [c][o]
    for (int n = tid; n < OCH * CH; n += 128) {
        float m = pg_b[n];
        const float* w = pg_w + n * CONDN;
#pragma unroll
        for (int k = 0; k < CONDN; k++) m += w[k] * c2[k];
        int o = n >> 6, c = n & 63;
        g_pw[b * (OCH * CH) + c * OCH + o] = fmaxf(m, 0.f);
    }
    // dynamic bias: 64 outputs (no relu)
    for (int n = tid; n < OCH; n += 128) {
        float m = bg_b[n];
        const float* w = bg_w + n * CONDN;
#pragma unroll
        for (int k = 0; k < CONDN; k++) m += w[k] * c2[k];
        g_db[b * OCH + n] = m;
    }
}

// =============================================================================
// K3: fused per-sample depthwise 3x3 (pad 1) + pointwise 1x1 + dynamic bias.
// 16x16 spatial tile per block, 4 chunks of 16 input channels.
// Output accumulators packed as f32x2 -> fma.rn.f32x2 halves FFMA issue count.
// =============================================================================
#define CCHUNK 16
__global__ void __launch_bounds__(256, 2)
k_main(const float* __restrict__ x, float* __restrict__ out) {
    __shared__ __align__(16) float xs[CCHUNK][18 * 18];
    __shared__ __align__(16) float pwsh[CCHUNK][OCH];
    __shared__ float dwsh[CH * KK];
    __shared__ float dbsh[OCH];

    int b    = blockIdx.y;
    int tile = blockIdx.x;                 // 0..63
    int bx = tile & 7, by = tile >> 3;
    int tid = threadIdx.x;                 // 256
    int tx = tid & 15, ty = tid >> 4;

    for (int i = tid; i < CH * KK; i += 256) dwsh[i] = g_dw[b * (CH * KK) + i];
    if (tid < OCH) dbsh[tid] = g_db[b * OCH + tid];

    unsigned long long acc2[OCH / 2];

    const int row0 = by * 16 - 1;
    const int col0 = bx * 16 - 1;

    for (int cc = 0; cc < CH / CCHUNK; cc++) {
        // ---- stage x tile (with halo) for this channel chunk ----
        for (int idx = tid; idx < CCHUNK * 324; idx += 256) {
            int c   = idx / 324;
            int rem = idx - c * 324;
            int row = rem / 18;
            int col = rem - row * 18;
            int gy = row0 + row;
            int gx = col0 + col;
            float v = 0.f;
            if (gy >= 0 && gy < HW && gx >= 0 && gx < HW)
                v = x[((size_t)(b * CH + cc * CCHUNK + c)) * NPIX + gy * HW + gx];
            xs[c][rem] = v;
        }
        // ---- stage pointwise weights for this chunk ----
        for (int idx = tid; idx < CCHUNK * OCH; idx += 256) {
            int c = idx >> 6, o = idx & 63;
            pwsh[c][o] = g_pw[b * (OCH * CH) + (cc * CCHUNK + c) * OCH + o];
        }
        __syncthreads();

        if (cc == 0) {
#pragma unroll
            for (int k = 0; k < OCH / 2; k++) {
                unsigned int lo = __float_as_uint(dbsh[2 * k]);
                unsigned int hi = __float_as_uint(dbsh[2 * k + 1]);
                asm("mov.b64 %0, {%1, %2};" : "=l"(acc2[k]) : "r"(lo), "r"(hi));
            }
        }

#pragma unroll 4
        for (int c = 0; c < CCHUNK; c++) {
            const float* xc  = &xs[c][ty * 18 + tx];
            const float* dwc = &dwsh[(cc * CCHUNK + c) * KK];
            float y = xc[0]  * dwc[0] + xc[1]  * dwc[1] + xc[2]  * dwc[2]
                    + xc[18] * dwc[3] + xc[19] * dwc[4] + xc[20] * dwc[5]
                    + xc[36] * dwc[6] + xc[37] * dwc[7] + xc[38] * dwc[8];

            unsigned long long yy;
            {
                unsigned int yu = __float_as_uint(y);
                asm("mov.b64 %0, {%1, %1};" : "=l"(yy) : "r"(yu));
            }
            const unsigned long long* pw2 =
                reinterpret_cast<const unsigned long long*>(&pwsh[c][0]);
#pragma unroll
            for (int k = 0; k < OCH / 2; k++) {
                asm("fma.rn.f32x2 %0, %1, %2, %0;"
                    : "+l"(acc2[k]) : "l"(yy), "l"(pw2[k]));
            }
        }
        __syncthreads();
    }

    // ---- store ----
    int gy = by * 16 + ty, gx = bx * 16 + tx;
    float* op = out + (size_t)(b * OCH) * NPIX + gy * HW + gx;
#pragma unroll
    for (int k = 0; k < OCH / 2; k++) {
        unsigned int lo, hi;
        asm("mov.b64 {%0, %1}, %2;" : "=r"(lo), "=r"(hi) : "l"(acc2[k]));
        op[(size_t)(2 * k) * NPIX]     = __uint_as_float(lo);
        op[(size_t)(2 * k + 1) * NPIX] = __uint_as_float(hi);
    }
}

// =============================================================================
// K4: per-(b,o)-plane partial sum / sum-of-squares (deterministic, no atomics)
// =============================================================================
__global__ void k_stats(const float* __restrict__ out) {
    int plane = blockIdx.x;   // b*64 + o
    const float4* p = reinterpret_cast<const float4*>(out + (size_t)plane * NPIX);
    int tid = threadIdx.x;    // 256
    float s = 0.f, q = 0.f;
    for (int i = tid; i < NPIX / 4; i += 256) {
        float4 v = p[i];
        s += v.x + v.y + v.z + v.w;
        q += v.x * v.x + v.y * v.y + v.z * v.z + v.w * v.w;
    }
#pragma unroll
    for (int off = 16; off > 0; off >>= 1) {
        s += __shfl_xor_sync(0xffffffffu, s, off);
        q += __shfl_xor_sync(0xffffffffu, q, off);
    }
    __shared__ float ss[8], qq[8];
    int lane = tid & 31, w = tid >> 5;
    if (lane == 0) { ss[w] = s; qq[w] = q; }
    __syncthreads();
    if (tid == 0) {
        float S = 0.f, Q = 0.f;
#pragma unroll
        for (int w2 = 0; w2 < 8; w2++) { S += ss[w2]; Q += qq[w2]; }
        g_part[plane * 2]     = S;
        g_part[plane * 2 + 1] = Q;
    }
}

// =============================================================================
// K5: fold partials -> per-channel scale/shift (deterministic)
// =============================================================================
__global__ void k_finalize(const float* __restrict__ gamma,
                           const float* __restrict__ beta) {
    int o = threadIdx.x;   // 64
    float S = 0.f, Q = 0.f;
    for (int b = 0; b < BATCH; b++) {
        S += g_part[(b * OCH + o) * 2];
        Q += g_part[(b * OCH + o) * 2 + 1];
    }
    const float inv = 1.0f / (float)(BATCH * NPIX);   // 1/524288
    float mean = S * inv;
    float var  = Q * inv - mean * mean;
    float sc = gamma[o] * rsqrtf(var + 1e-5f);
    g_scale[o] = sc;
    g_shift[o] = beta[o] - mean * sc;
}

// =============================================================================
// K6: in-place normalize
// =============================================================================
__global__ void k_norm(float* __restrict__ out) {
    int plane = blockIdx.x;
    int o = plane & 63;
    float sc = g_scale[o], sh = g_shift[o];
    float4* p = reinterpret_cast<float4*>(out + (size_t)plane * NPIX);
    int tid = threadIdx.x;   // 256
    for (int i = tid; i < NPIX / 4; i += 256) {
        float4 v = p[i];
        v.x = v.x * sc + sh;
        v.y = v.y * sc + sh;
        v.z = v.z * sc + sh;
        v.w = v.w * sc + sh;
        p[i] = v;
    }
}

// =============================================================================
extern "C" void kernel_launch(void* const* d_in, const int* in_sizes, int n_in,
                              void* d_out, int out_size) {
    const float* x      = (const float*)d_in[0];
    const float* cg_w1  = (const float*)d_in[1];
    const float* cg_b1  = (const float*)d_in[2];
    const float* cg_w2  = (const float*)d_in[3];
    const float* cg_b2  = (const float*)d_in[4];
    const float* wg_w   = (const float*)d_in[5];
    const float* wg_b   = (const float*)d_in[6];
    const float* pg_w   = (const float*)d_in[7];
    const float* pg_b   = (const float*)d_in[8];
    const float* bg_w   = (const float*)d_in[9];
    const float* bg_b   = (const float*)d_in[10];
    const float* bn_g   = (const float*)d_in[11];
    const float* bn_b   = (const float*)d_in[12];
    float* out = (float*)d_out;

    k_ssum<<<BATCH * CH, 256>>>(x);
    k_cond<<<BATCH, 128>>>(cg_w1, cg_b1, cg_w2, cg_b2,
                           wg_w, wg_b, pg_w, pg_b, bg_w, bg_b);
    dim3 g3(64, BATCH);
    k_main<<<g3, 256>>>(x, out);
    k_stats<<<BATCH * OCH, 256>>>(out);
    k_finalize<<<1, OCH>>>(bn_g, bn_b);
    k_norm<<<BATCH * OCH, 256>>>(out);
}

// round 6
// speedup vs baseline: 1.2796x; 1.2796x over previous
#include <cuda_runtime.h>
#include <cstdint>

#define BATCH 32
#define CH    64
#define OCH   64
#define HW    128
#define NPIX  16384
#define CONDN 16
#define KK    9

// ---------------- scratch (device globals; no allocation allowed) -------------
__device__ float g_S[BATCH * CH * KK];        // strided sums  [b][c][i*3+j]
__device__ float g_dw[BATCH * CH * KK];       // depthwise weights
__device__ float g_pw[BATCH * CH * OCH];      // pointwise, stored [b][c][o]
__device__ float g_db[BATCH * OCH];           // dynamic bias
__device__ float g_part[BATCH * OCH * 2];     // per-(b,o) partial sum / sumsq
__device__ float g_scale[OCH];
__device__ float g_shift[OCH];

// =============================================================================
// K1: strided partial sums S[b,c,i,j] = sum_{p,q=0..62} x[b,c,2p+i,2q+j]
// =============================================================================
__global__ void k_ssum(const float* __restrict__ x) {
    int bc = blockIdx.x;                       // b*64 + c
    const float* xp = x + (size_t)bc * NPIX;
    int tid = threadIdx.x;                     // 256
    int s = tid & 127;                         // fixed column per thread
    int rbase = tid >> 7;                      // 0 or 1 -> fixed row parity

    float a[9];
#pragma unroll
    for (int m = 0; m < 9; m++) a[m] = 0.f;

    bool se = (s & 1) == 0;
    bool j0 = se && (s <= 124);
    bool j1 = (!se) && (s <= 125);
    bool j2 = se && (s >= 2);

    for (int k = 0; k < 64; k++) {
        int r = rbase + 2 * k;
        float v = xp[r * HW + s];
        bool re = (r & 1) == 0;
        bool i0 = re && (r <= 124);
        bool i1 = (!re) && (r <= 125);
        bool i2 = re && (r >= 2);
        if (i0) { if (j0) a[0] += v; if (j1) a[1] += v; if (j2) a[2] += v; }
        if (i1) { if (j0) a[3] += v; if (j1) a[4] += v; if (j2) a[5] += v; }
        if (i2) { if (j0) a[6] += v; if (j1) a[7] += v; if (j2) a[8] += v; }
    }

#pragma unroll
    for (int m = 0; m < 9; m++)
#pragma unroll
        for (int off = 16; off > 0; off >>= 1)
            a[m] += __shfl_xor_sync(0xffffffffu, a[m], off);

    __shared__ float red[8][9];
    int lane = tid & 31, w = tid >> 5;
    if (lane == 0) {
#pragma unroll
        for (int m = 0; m < 9; m++) red[w][m] = a[m];
    }
    __syncthreads();
    if (tid < 9) {
        float t = 0.f;
#pragma unroll
        for (int w2 = 0; w2 < 8; w2++) t += red[w2][tid];
        g_S[bc * 9 + tid] = t;
    }
}

// =============================================================================
// K2: conditioning network + dynamic weight generators (one block per sample)
// =============================================================================
__global__ void k_cond(const float* __restrict__ cg_w1, const float* __restrict__ cg_b1,
                       const float* __restrict__ cg_w2, const float* __restrict__ cg_b2,
                       const float* __restrict__ wg_w,  const float* __restrict__ wg_b,
                       const float* __restrict__ pg_w,  const float* __restrict__ pg_b,
                       const float* __restrict__ bg_w,  const float* __restrict__ bg_b) {
    int b = blockIdx.x;
    int tid = threadIdx.x;   // 128
    __shared__ float Ssh[CH * KK];      // 576
    __shared__ float c1[CONDN];
    __shared__ float c2[CONDN];

    for (int i = tid; i < CH * KK; i += 128) Ssh[i] = g_S[b * (CH * KK) + i];
    __syncthreads();

    if (tid < CONDN) {
        float m = 0.f;
        const float* w = cg_w1 + tid * (CH * KK);
        for (int i = 0; i < CH * KK; i++) m += w[i] * Ssh[i];
        m = m * (1.0f / 3969.0f) + cg_b1[tid];
        c1[tid] = fmaxf(m, 0.f);
    }
    __syncthreads();
    if (tid < CONDN) {
        float m = cg_b2[tid];
#pragma unroll
        for (int k = 0; k < CONDN; k++) m += cg_w2[tid * CONDN + k] * c1[k];
        c2[tid] = fmaxf(m, 0.f);
    }
    __syncthreads();

    for (int n = tid; n < CH * KK; n += 128) {
        float m = wg_b[n];
        const float* w = wg_w + n * CONDN;
#pragma unroll
        for (int k = 0; k < CONDN; k++) m += w[k] * c2[k];
        g_dw[b * (CH * KK) + n] = fmaxf(m, 0.f);
    }
    for (int n = tid; n < OCH * CH; n += 128) {
        float m = pg_b[n];
        const float* w = pg_w + n * CONDN;
#pragma unroll
        for (int k = 0; k < CONDN; k++) m += w[k] * c2[k];
        int o = n >> 6, c = n & 63;
        g_pw[b * (OCH * CH) + c * OCH + o] = fmaxf(m, 0.f);
    }
    for (int n = tid; n < OCH; n += 128) {
        float m = bg_b[n];
        const float* w = bg_w + n * CONDN;
#pragma unroll
        for (int k = 0; k < CONDN; k++) m += w[k] * c2[k];
        g_db[b * OCH + n] = m;
    }
}

// =============================================================================
// K3: fused depthwise 3x3 + pointwise + dynamic bias.
//  - 16x32 spatial tile, 2 adjacent pixels per thread (256 threads)
//  - 8 chunks of 8 input channels, cp.async double-buffered staging
//  - all smem reads vectorized (LDS.128 / LDS.64), accumulators in f32x2
// =============================================================================
#define CC8   8
#define XROW  36    // padded halo row width (34 used)

__device__ __forceinline__ void ffma2(unsigned long long& a,
                                      unsigned long long y,
                                      unsigned long long p) {
    asm("fma.rn.f32x2 %0, %1, %2, %0;" : "+l"(a) : "l"(y), "l"(p));
}
__device__ __forceinline__ unsigned long long dup2(float v) {
    unsigned long long r;
    asm("mov.b64 %0, {%1, %1};" : "=l"(r) : "r"(__float_as_uint(v)));
    return r;
}
__device__ __forceinline__ unsigned long long pack2(float lo, float hi) {
    unsigned long long r;
    asm("mov.b64 %0, {%1, %2};" : "=l"(r) : "r"(__float_as_uint(lo)), "r"(__float_as_uint(hi)));
    return r;
}

__global__ void __launch_bounds__(256, 1)
k_main(const float* __restrict__ x, float* __restrict__ out) {
    __shared__ __align__(16) float xs[2][CC8 * 18 * XROW];   // 2 x 20736 B
    __shared__ __align__(16) float pwsh[2][CC8 * OCH];       // 2 x 2048 B
    __shared__ __align__(16) float dwsh[CH * 12];            // padded to 12/channel
    __shared__ float dbsh[OCH];

    const int b    = blockIdx.y;
    const int tile = blockIdx.x;                 // 0..31
    const int col0 = (tile & 3) * 32;
    const int row0 = (tile >> 2) * 16;
    const int tid  = threadIdx.x;                // 256
    const int tx   = tid & 15, ty = tid >> 4;

    for (int i = tid; i < CH * KK; i += 256)
        dwsh[(i / 9) * 12 + (i % 9)] = g_dw[b * CH * KK + i];
    if (tid < OCH) dbsh[tid] = g_db[b * OCH + tid];

    auto stage = [&](int cc, int buf) {
        // x halo tile: 8 channels x 18 rows x 34 cols, 4B cp.async w/ zfill
        unsigned xsb = (unsigned)__cvta_generic_to_shared(&xs[buf][0]);
        for (int idx = tid; idx < CC8 * 18 * 34; idx += 256) {
            int c   = idx / (18 * 34);
            int rem = idx - c * (18 * 34);
            int row = rem / 34;
            int col = rem - row * 34;
            int gy = row0 - 1 + row;
            int gx = col0 - 1 + col;
            bool ok = (gy >= 0) & (gy < HW) & (gx >= 0) & (gx < HW);
            const float* gp = x + ((size_t)(b * CH + cc * CC8 + c) * NPIX
                                   + (ok ? (gy * HW + gx) : 0));
            unsigned dst = xsb + (unsigned)(((c * 18 + row) * XROW + col) * 4);
            int sz = ok ? 4 : 0;
            asm volatile("cp.async.ca.shared.global [%0], [%1], 4, %2;\n"
                         :: "r"(dst), "l"(gp), "r"(sz) : "memory");
        }
        // pw chunk: 8*64 floats = 128 x 16B
        if (tid < 128) {
            const float* src = g_pw + (size_t)b * CH * OCH + cc * CC8 * OCH + tid * 4;
            unsigned dst = (unsigned)__cvta_generic_to_shared(&pwsh[buf][0]) + tid * 16;
            asm volatile("cp.async.cg.shared.global [%0], [%1], 16;\n"
                         :: "r"(dst), "l"(src) : "memory");
        }
    };

    stage(0, 0);
    asm volatile("cp.async.commit_group;\n" ::: "memory");

    unsigned long long acc0[32], acc1[32];   // (2k,2k+1) output pair, pixels 0/1

    for (int cc = 0; cc < CH / CC8; cc++) {
        const int buf = cc & 1;
        if (cc < CH / CC8 - 1) {
            stage(cc + 1, buf ^ 1);
            asm volatile("cp.async.commit_group;\n" ::: "memory");
            asm volatile("cp.async.wait_group 1;\n" ::: "memory");
        } else {
            asm volatile("cp.async.wait_group 0;\n" ::: "memory");
        }
        __syncthreads();

        if (cc == 0) {
#pragma unroll
            for (int k = 0; k < 32; k++) {
                unsigned long long d = pack2(dbsh[2 * k], dbsh[2 * k + 1]);
                acc0[k] = d;
                acc1[k] = d;
            }
        }

        const float* xcbase = &xs[buf][0] + ty * XROW + 2 * tx;
#pragma unroll
        for (int c = 0; c < CC8; c++) {
            const float* xc = xcbase + c * 18 * XROW;
            float2 a0 = *(const float2*)(xc);
            float2 a1 = *(const float2*)(xc + 2);
            float2 b0 = *(const float2*)(xc + XROW);
            float2 b1 = *(const float2*)(xc + XROW + 2);
            float2 r0 = *(const float2*)(xc + 2 * XROW);
            float2 r1 = *(const float2*)(xc + 2 * XROW + 2);
            const float* w = &dwsh[(cc * CC8 + c) * 12];
            float4 w0 = *(const float4*)(w);
            float4 w1 = *(const float4*)(w + 4);
            float  w8 = w[8];

            float y0 = a0.x * w0.x + a0.y * w0.y + a1.x * w0.z
                     + b0.x * w0.w + b0.y * w1.x + b1.x * w1.y
                     + r0.x * w1.z + r0.y * w1.w + r1.x * w8;
            float y1 = a0.y * w0.x + a1.x * w0.y + a1.y * w0.z
                     + b0.y * w0.w + b1.x * w1.x + b1.y * w1.y
                     + r0.y * w1.z + r1.x * w1.w + r1.y * w8;

            unsigned long long yy0 = dup2(y0);
            unsigned long long yy1 = dup2(y1);
            const ulonglong2* pw2 = (const ulonglong2*)&pwsh[buf][c * OCH];
#pragma unroll
            for (int j = 0; j < 16; j++) {
                ulonglong2 q = pw2[j];
                ffma2(acc0[2 * j],     yy0, q.x);
                ffma2(acc0[2 * j + 1], yy0, q.y);
                ffma2(acc1[2 * j],     yy1, q.x);
                ffma2(acc1[2 * j + 1], yy1, q.y);
            }
        }
        __syncthreads();
    }

    // ---- store: 2 adjacent pixels -> STG.64 per output channel ----
    const int gy = row0 + ty;
    const int gx = col0 + 2 * tx;
    float* op = out + (size_t)(b * OCH) * NPIX + gy * HW + gx;
#pragma unroll
    for (int k = 0; k < 32; k++) {
        unsigned long long v0 = acc0[k], v1 = acc1[k];
        float p0lo = __uint_as_float((unsigned)(v0 & 0xffffffffu));
        float p0hi = __uint_as_float((unsigned)(v0 >> 32));
        float p1lo = __uint_as_float((unsigned)(v1 & 0xffffffffu));
        float p1hi = __uint_as_float((unsigned)(v1 >> 32));
        *(float2*)(op + (size_t)(2 * k) * NPIX)     = make_float2(p0lo, p1lo);
        *(float2*)(op + (size_t)(2 * k + 1) * NPIX) = make_float2(p0hi, p1hi);
    }
}

// =============================================================================
// K4: per-(b,o)-plane partial sum / sum-of-squares (deterministic)
// =============================================================================
__global__ void k_stats(const float* __restrict__ out) {
    int plane = blockIdx.x;   // b*64 + o
    const float4* p = reinterpret_cast<const float4*>(out + (size_t)plane * NPIX);
    int tid = threadIdx.x;    // 256
    float s = 0.f, q = 0.f;
    for (int i = tid; i < NPIX / 4; i += 256) {
        float4 v = p[i];
        s += v.x + v.y + v.z + v.w;
        q += v.x * v.x + v.y * v.y + v.z * v.z + v.w * v.w;
    }
#pragma unroll
    for (int off = 16; off > 0; off >>= 1) {
        s += __shfl_xor_sync(0xffffffffu, s, off);
        q += __shfl_xor_sync(0xffffffffu, q, off);
    }
    __shared__ float ss[8], qq[8];
    int lane = tid & 31, w = tid >> 5;
    if (lane == 0) { ss[w] = s; qq[w] = q; }
    __syncthreads();
    if (tid == 0) {
        float S = 0.f, Q = 0.f;
#pragma unroll
        for (int w2 = 0; w2 < 8; w2++) { S += ss[w2]; Q += qq[w2]; }
        g_part[plane * 2]     = S;
        g_part[plane * 2 + 1] = Q;
    }
}

// =============================================================================
// K5: fold partials -> per-channel scale/shift (deterministic)
// =============================================================================
__global__ void k_finalize(const float* __restrict__ gamma,
                           const float* __restrict__ beta) {
    int o = threadIdx.x;   // 64
    float S = 0.f, Q = 0.f;
    for (int b = 0; b < BATCH; b++) {
        S += g_part[(b * OCH + o) * 2];
        Q += g_part[(b * OCH + o) * 2 + 1];
    }
    const float inv = 1.0f / (float)(BATCH * NPIX);
    float mean = S * inv;
    float var  = Q * inv - mean * mean;
    float sc = gamma[o] * rsqrtf(var + 1e-5f);
    g_scale[o] = sc;
    g_shift[o] = beta[o] - mean * sc;
}

// =============================================================================
// K6: in-place normalize
// =============================================================================
__global__ void k_norm(float* __restrict__ out) {
    int plane = blockIdx.x;
    int o = plane & 63;
    float sc = g_scale[o], sh = g_shift[o];
    float4* p = reinterpret_cast<float4*>(out + (size_t)plane * NPIX);
    int tid = threadIdx.x;   // 256
    for (int i = tid; i < NPIX / 4; i += 256) {
        float4 v = p[i];
        v.x = v.x * sc + sh;
        v.y = v.y * sc + sh;
        v.z = v.z * sc + sh;
        v.w = v.w * sc + sh;
        p[i] = v;
    }
}

// =============================================================================
extern "C" void kernel_launch(void* const* d_in, const int* in_sizes, int n_in,
                              void* d_out, int out_size) {
    const float* x      = (const float*)d_in[0];
    const float* cg_w1  = (const float*)d_in[1];
    const float* cg_b1  = (const float*)d_in[2];
    const float* cg_w2  = (const float*)d_in[3];
    const float* cg_b2  = (const float*)d_in[4];
    const float* wg_w   = (const float*)d_in[5];
    const float* wg_b   = (const float*)d_in[6];
    const float* pg_w   = (const float*)d_in[7];
    const float* pg_b   = (const float*)d_in[8];
    const float* bg_w   = (const float*)d_in[9];
    const float* bg_b   = (const float*)d_in[10];
    const float* bn_g   = (const float*)d_in[11];
    const float* bn_b   = (const float*)d_in[12];
    float* out = (float*)d_out;

    k_ssum<<<BATCH * CH, 256>>>(x);
    k_cond<<<BATCH, 128>>>(cg_w1, cg_b1, cg_w2, cg_b2,
                           wg_w, wg_b, pg_w, pg_b, bg_w, bg_b);
    dim3 g3(32, BATCH);
    k_main<<<g3, 256>>>(x, out);
    k_stats<<<BATCH * OCH, 256>>>(out);
    k_finalize<<<1, OCH>>>(bn_g, bn_b);
    k_norm<<<BATCH * OCH, 256>>>(out);
}